// round 15
// baseline (speedup 1.0000x reference)
#include <cuda_runtime.h>

#define NN 50000
#define NE 800000
#define NG 128
#define D  64
#define NL 4
#define BN_EPS 1e-5f

#define NBLK 296
#define TPB  512
#define NWARP (TPB / 32)          // 16
#define GSZ  (NBLK * TPB)         // 151552
#define NPW  4
#define NGRP (NN / NPW)           // 12500 exact
#define CHK  170                  // ceil(NN / NBLK)

typedef unsigned long long ull;

// ---------------- device scratch ----------------
__device__ int   g_deg[NN];
__device__ int   g_off[NN + 1];
__device__ int   g_cur[NN];
__device__ __align__(8) int2 g_edge[NE];      // {src, float_bits(w)}
__device__ __align__(16) float g_h[NN * D];
__device__ __align__(16) float g_t[NN * D];
__device__ float g_stats[NL * 4 * D];
__device__ float g_pool[(NL + 1) * NG * D];
__device__ int   g_gstart[NG + 1];
__device__ int   g_bsum[NBLK];
__device__ unsigned g_tick[8];
__device__ unsigned g_barcnt;
__device__ unsigned g_bargen;

// ---------------- f32x2 helpers ----------------
__device__ __forceinline__ ull ffma2(ull a, ull b, ull c) {
    ull d; asm("fma.rn.f32x2 %0, %1, %2, %3;" : "=l"(d) : "l"(a), "l"(b), "l"(c)); return d;
}
__device__ __forceinline__ ull fpack2(float lo, float hi) {
    ull d; asm("mov.b64 %0, {%1, %2};" : "=l"(d) : "f"(lo), "f"(hi)); return d;
}
__device__ __forceinline__ ull wdup(int bits) {
    float f = __int_as_float(bits);
    return fpack2(f, f);
}
__device__ __forceinline__ float2 funpack2(ull a) {
    float lo, hi; asm("mov.b64 {%0, %1}, %2;" : "=f"(lo), "=f"(hi) : "l"(a));
    return make_float2(lo, hi);
}

// clamped edge load: duplicate last edge with zero weight beyond e1
__device__ __forceinline__ int2 ldedge(int e, int e1) {
    int idx = min(e, e1 - 1);
    int2 d = g_edge[idx];
    if (e >= e1) d.y = 0;        // 0x0 == 0.0f
    return d;
}

// ---------------- software grid barrier (all 296 CTAs resident) ----------------
__device__ __forceinline__ void gsync() {
    __syncthreads();
    if (threadIdx.x == 0) {
        unsigned gen = *(volatile unsigned*)&g_bargen;
        __threadfence();
        unsigned t = atomicAdd(&g_barcnt, 1u);
        if (t == NBLK - 1) {
            g_barcnt = 0;
            __threadfence();
            atomicAdd(&g_bargen, 1u);
        } else {
            while (*(volatile unsigned*)&g_bargen == gen) __nanosleep(64);
        }
        __threadfence();
    }
    __syncthreads();
}

// ---------------- graph pooling (block-wide, blocks < NG only) ----------------
__device__ __forceinline__ void pool_block(const float* __restrict__ h, int pidx, int g,
                                           float* scr) {
    const int tid = threadIdx.x, warp = tid >> 5, lane = tid & 31, f0 = lane * 2;
    const int n0 = g_gstart[g], n1 = g_gstart[g + 1];
    float2 acc = make_float2(0.f, 0.f);
    for (int n = n0 + warp; n < n1; n += NWARP) {
        float2 v = *(const float2*)(h + (size_t)n * D + f0);
        acc.x += v.x; acc.y += v.y;
    }
    scr[warp * D + f0] = acc.x;
    scr[warp * D + f0 + 1] = acc.y;
    __syncthreads();
    if (tid < D) {
        float s = 0.f;
        #pragma unroll
        for (int w2 = 0; w2 < NWARP; w2++) s += scr[w2 * D + tid];
        g_pool[((size_t)pidx * NG + g) * D + tid] = s;
    }
    __syncthreads();
}

__global__ __launch_bounds__(TPB, 2) void k_gin(
    const float* __restrict__ x, const float* __restrict__ w,
    const int* __restrict__ src, const int* __restrict__ dst,
    const int* __restrict__ gids, const float* __restrict__ epsv,
    const float* __restrict__ W1, const float* __restrict__ b1,
    const float* __restrict__ mbng, const float* __restrict__ mbnb,
    const float* __restrict__ W2, const float* __restrict__ b2,
    const float* __restrict__ bng, const float* __restrict__ bnb,
    const float* __restrict__ predW, const float* __restrict__ predb,
    float* __restrict__ out)
{
    __shared__ __align__(16) ull   sWp[2048];              // 16 KB (scan overlay)
    __shared__ __align__(16) float srow[NWARP * NPW * D];  // 16 KB (pool overlay)
    __shared__ float s_red[2 * D];

    const int tid = threadIdx.x, bid = blockIdx.x;
    const int gtid = bid * TPB + tid;
    const int warp = tid >> 5, lane = tid & 31;
    const int f0 = lane * 2;
    float* myrow = srow + warp * (NPW * D);

    // ---------- phase 0 ----------
    if (gtid < NN) g_deg[gtid] = 0;
    if (gtid < NL * 4 * D) g_stats[gtid] = 0.f;
    if (gtid < 8) g_tick[gtid] = 0u;
    if (bid == 0 && tid <= NG) {
        if (tid == NG) g_gstart[NG] = NN;
        else {
            int lo = 0, hi = NN;
            while (lo < hi) {
                int m = (lo + hi) >> 1;
                if (gids[m] < tid) lo = m + 1; else hi = m;
            }
            g_gstart[tid] = lo;
        }
    }
    gsync();

    // ---------- phase 1: degree histogram ----------
    for (int e = gtid; e < NE; e += GSZ) atomicAdd(&g_deg[dst[e]], 1);
    gsync();

    // ---------- phase 2a: block-local scan (CHK=170 <= 256) ----------
    int* s_scan = (int*)sWp;
    {
        int node = bid * CHK + tid;
        int dv = 0;
        if (tid < CHK && node < NN) dv = g_deg[node];
        if (tid < 256) s_scan[tid] = (tid < CHK) ? dv : 0;
        __syncthreads();
        for (int off = 1; off < 256; off <<= 1) {
            int v = 0;
            if (tid < 256 && tid >= off) v = s_scan[tid - off];
            __syncthreads();
            if (tid < 256) s_scan[tid] += v;
            __syncthreads();
        }
        if (tid < CHK && node < NN) g_off[node] = s_scan[tid] - dv;
        if (tid == 0) g_bsum[bid] = s_scan[255];
    }
    gsync();

    // ---------- phase 2b: scan 296 block totals ----------
    {
        int v = 0;
        if (tid < 512) { v = (tid < NBLK) ? g_bsum[tid] : 0; s_scan[tid] = v; }
        __syncthreads();
        for (int off = 1; off < 512; off <<= 1) {
            int u = 0;
            if (tid < 512 && tid >= off) u = s_scan[tid - off];
            __syncthreads();
            if (tid < 512) s_scan[tid] += u;
            __syncthreads();
        }
        if (tid < 512) s_scan[512 + tid] = s_scan[tid] - v;
        __syncthreads();
        int prefix = s_scan[512 + bid];
        int node = bid * CHK + tid;
        if (tid < CHK && node < NN) {
            int o = g_off[node] + prefix;
            g_off[node] = o; g_cur[node] = o;
        }
        if (bid == 0 && tid == 0) g_off[NN] = s_scan[NBLK - 1];
    }
    gsync();

    // ---------- phase 3: scatter edges + pool0 ----------
    for (int e = gtid; e < NE; e += GSZ) {
        int dn = dst[e];
        int p = atomicAdd(&g_cur[dn], 1);
        g_edge[p] = make_int2(src[e], __float_as_int(w[e]));
    }
    if (bid < NG) pool_block(x, 0, bid, srow);
    gsync();

    // ---------- layers ----------
    for (int l = 0; l < NL; l++) {
        // ===== phase A: aggregate (predicated 8-wide pipeline) + GEMM1 + stats1 =====
        {
            const float* W1l = W1 + (size_t)l * D * D;
            for (int i = tid; i < 2048; i += TPB) {
                int k2 = i >> 6, f = i & 63;
                sWp[i] = fpack2(W1l[(2 * k2) * D + f], W1l[(2 * k2 + 1) * D + f]);
            }
            if (tid < 2 * D) s_red[tid] = 0.f;
            __syncthreads();
            if (l > 0 && bid < NG) pool_block(g_h, l, bid, srow);
            __syncthreads();

            const float* hin = (l == 0) ? x : g_h;
            const float ep1 = 1.0f + epsv[l];
            const ull ep2 = fpack2(ep1, ep1);
            float2 bb = *(const float2*)(b1 + (size_t)l * D + f0);
            float2 psum = make_float2(0.f, 0.f), psq = make_float2(0.f, 0.f);

            for (;;) {
                unsigned g = 0;
                if (lane == 0) g = atomicAdd(&g_tick[l], 1u);
                g = __shfl_sync(0xffffffffu, g, 0);
                if (g >= NGRP) break;
                const int base = (int)g * NPW;

                // lane-owns-features gather: predicated 8-wide pipeline, no tail
                #pragma unroll 1
                for (int j = 0; j < NPW; j++) {
                    const int n = base + j;
                    const int e0 = g_off[n], e1 = g_off[n + 1];
                    ull acc = 0;
                    if (e0 < e1) {
                        int2 d0 = ldedge(e0, e1),     d1 = ldedge(e0 + 1, e1);
                        int2 d2 = ldedge(e0 + 2, e1), d3 = ldedge(e0 + 3, e1);
                        int2 d4 = ldedge(e0 + 4, e1), d5 = ldedge(e0 + 5, e1);
                        int2 d6 = ldedge(e0 + 6, e1), d7 = ldedge(e0 + 7, e1);
                        int eb = e0;
                        #pragma unroll 1
                        for (;;) {
                            const int nb = eb + 8;
                            const bool more = nb < e1;
                            int2 p0, p1, p2, p3, p4, p5, p6, p7;
                            if (more) {
                                p0 = ldedge(nb, e1);     p1 = ldedge(nb + 1, e1);
                                p2 = ldedge(nb + 2, e1); p3 = ldedge(nb + 3, e1);
                                p4 = ldedge(nb + 4, e1); p5 = ldedge(nb + 5, e1);
                                p6 = ldedge(nb + 6, e1); p7 = ldedge(nb + 7, e1);
                            }
                            ull h0 = *(const ull*)(hin + (size_t)d0.x * D + f0);
                            ull h1 = *(const ull*)(hin + (size_t)d1.x * D + f0);
                            ull h2 = *(const ull*)(hin + (size_t)d2.x * D + f0);
                            ull h3 = *(const ull*)(hin + (size_t)d3.x * D + f0);
                            ull h4 = *(const ull*)(hin + (size_t)d4.x * D + f0);
                            ull h5 = *(const ull*)(hin + (size_t)d5.x * D + f0);
                            ull h6 = *(const ull*)(hin + (size_t)d6.x * D + f0);
                            ull h7 = *(const ull*)(hin + (size_t)d7.x * D + f0);
                            acc = ffma2(h0, wdup(d0.y), acc);
                            acc = ffma2(h1, wdup(d1.y), acc);
                            acc = ffma2(h2, wdup(d2.y), acc);
                            acc = ffma2(h3, wdup(d3.y), acc);
                            acc = ffma2(h4, wdup(d4.y), acc);
                            acc = ffma2(h5, wdup(d5.y), acc);
                            acc = ffma2(h6, wdup(d6.y), acc);
                            acc = ffma2(h7, wdup(d7.y), acc);
                            if (!more) break;
                            d0 = p0; d1 = p1; d2 = p2; d3 = p3;
                            d4 = p4; d5 = p5; d6 = p6; d7 = p7;
                            eb = nb;
                        }
                    }
                    ull hn = *(const ull*)(hin + (size_t)n * D + f0);
                    *(ull*)(myrow + j * D + f0) = ffma2(hn, ep2, acc);
                }
                __syncwarp();

                // GEMM1: NPW-node blocking, 16B weight loads + 16B h broadcasts
                ull acc0[NPW], acc1[NPW];
                #pragma unroll
                for (int j = 0; j < NPW; j++) { acc0[j] = 0; acc1[j] = 0; }
                #pragma unroll
                for (int k2 = 0; k2 < 32; k2 += 2) {
                    ulonglong2 w0 = *(const ulonglong2*)(sWp + k2 * D + f0);
                    ulonglong2 w1 = *(const ulonglong2*)(sWp + (k2 + 1) * D + f0);
                    #pragma unroll
                    for (int j = 0; j < NPW; j++) {
                        ulonglong2 h2 = *(const ulonglong2*)(myrow + j * D + 2 * k2);
                        acc0[j] = ffma2(h2.x, w0.x, acc0[j]);
                        acc1[j] = ffma2(h2.x, w0.y, acc1[j]);
                        acc0[j] = ffma2(h2.y, w1.x, acc0[j]);
                        acc1[j] = ffma2(h2.y, w1.y, acc1[j]);
                    }
                }
                #pragma unroll
                for (int j = 0; j < NPW; j++) {
                    float2 u0 = funpack2(acc0[j]), u1 = funpack2(acc1[j]);
                    float ax = u0.x + u0.y + bb.x;
                    float ay = u1.x + u1.y + bb.y;
                    *(float2*)(g_t + (size_t)(base + j) * D + f0) = make_float2(ax, ay);
                    psum.x += ax; psum.y += ay;
                    psq.x = fmaf(ax, ax, psq.x);
                    psq.y = fmaf(ay, ay, psq.y);
                }
                __syncwarp();
            }
            atomicAdd(&s_red[f0], psum.x);
            atomicAdd(&s_red[f0 + 1], psum.y);
            atomicAdd(&s_red[D + f0], psq.x);
            atomicAdd(&s_red[D + f0 + 1], psq.y);
            __syncthreads();
            if (tid < D) {
                atomicAdd(&g_stats[(l * 4 + 0) * D + tid], s_red[tid]);
                atomicAdd(&g_stats[(l * 4 + 1) * D + tid], s_red[D + tid]);
            }
        }
        gsync();

        // ===== phase B: BN1 + ReLU + GEMM2 + stats2 =====
        {
            const float* W2l = W2 + (size_t)l * D * D;
            for (int i = tid; i < 2048; i += TPB) {
                int k2 = i >> 6, f = i & 63;
                sWp[i] = fpack2(W2l[(2 * k2) * D + f], W2l[(2 * k2 + 1) * D + f]);
            }
            if (tid < 2 * D) s_red[tid] = 0.f;
            __syncthreads();

            const float invN = 1.0f / NN;
            const float* sum1 = g_stats + (l * 4 + 0) * D;
            const float* sq1  = g_stats + (l * 4 + 1) * D;
            float mu0 = sum1[f0] * invN, mu1 = sum1[f0 + 1] * invN;
            float v0 = sq1[f0] * invN - mu0 * mu0;
            float v1 = sq1[f0 + 1] * invN - mu1 * mu1;
            float sc0 = mbng[l * D + f0] * rsqrtf(v0 + BN_EPS);
            float sc1 = mbng[l * D + f0 + 1] * rsqrtf(v1 + BN_EPS);
            float sh0 = mbnb[l * D + f0] - mu0 * sc0;
            float sh1 = mbnb[l * D + f0 + 1] - mu1 * sc1;
            float2 bb = *(const float2*)(b2 + (size_t)l * D + f0);
            float2 psum = make_float2(0.f, 0.f), psq = make_float2(0.f, 0.f);

            for (;;) {
                unsigned g = 0;
                if (lane == 0) g = atomicAdd(&g_tick[4 + l], 1u);
                g = __shfl_sync(0xffffffffu, g, 0);
                if (g >= NGRP) break;
                const int base = (int)g * NPW;

                #pragma unroll
                for (int j = 0; j < NPW; j++) {
                    float2 t2 = *(const float2*)(g_t + (size_t)(base + j) * D + f0);
                    float u0 = fmaxf(fmaf(t2.x, sc0, sh0), 0.f);
                    float u1 = fmaxf(fmaf(t2.y, sc1, sh1), 0.f);
                    *(float2*)(myrow + j * D + f0) = make_float2(u0, u1);
                }
                __syncwarp();

                ull acc0[NPW], acc1[NPW];
                #pragma unroll
                for (int j = 0; j < NPW; j++) { acc0[j] = 0; acc1[j] = 0; }
                #pragma unroll
                for (int k2 = 0; k2 < 32; k2 += 2) {
                    ulonglong2 w0 = *(const ulonglong2*)(sWp + k2 * D + f0);
                    ulonglong2 w1 = *(const ulonglong2*)(sWp + (k2 + 1) * D + f0);
                    #pragma unroll
                    for (int j = 0; j < NPW; j++) {
                        ulonglong2 h2 = *(const ulonglong2*)(myrow + j * D + 2 * k2);
                        acc0[j] = ffma2(h2.x, w0.x, acc0[j]);
                        acc1[j] = ffma2(h2.x, w0.y, acc1[j]);
                        acc0[j] = ffma2(h2.y, w1.x, acc0[j]);
                        acc1[j] = ffma2(h2.y, w1.y, acc1[j]);
                    }
                }
                #pragma unroll
                for (int j = 0; j < NPW; j++) {
                    float2 u0 = funpack2(acc0[j]), u1 = funpack2(acc1[j]);
                    float ax = u0.x + u0.y + bb.x;
                    float ay = u1.x + u1.y + bb.y;
                    *(float2*)(g_t + (size_t)(base + j) * D + f0) = make_float2(ax, ay);
                    psum.x += ax; psum.y += ay;
                    psq.x = fmaf(ax, ax, psq.x);
                    psq.y = fmaf(ay, ay, psq.y);
                }
                __syncwarp();
            }
            atomicAdd(&s_red[f0], psum.x);
            atomicAdd(&s_red[f0 + 1], psum.y);
            atomicAdd(&s_red[D + f0], psq.x);
            atomicAdd(&s_red[D + f0 + 1], psq.y);
            __syncthreads();
            if (tid < D) {
                atomicAdd(&g_stats[(l * 4 + 2) * D + tid], s_red[tid]);
                atomicAdd(&g_stats[(l * 4 + 3) * D + tid], s_red[D + tid]);
            }
        }
        gsync();

        // ===== phase C: outer BN + ReLU -> g_h =====
        {
            if (tid < D) {
                const float invN = 1.0f / NN;
                float mu = g_stats[(l * 4 + 2) * D + tid] * invN;
                float var = g_stats[(l * 4 + 3) * D + tid] * invN - mu * mu;
                float sc = bng[l * D + tid] * rsqrtf(var + BN_EPS);
                s_red[tid] = sc;
                s_red[D + tid] = bnb[l * D + tid] - mu * sc;
            }
            __syncthreads();
            for (int i4 = gtid; i4 < NN * (D / 4); i4 += GSZ) {
                int fb = (i4 & 15) * 4;
                float4 t = *(const float4*)(g_t + (size_t)i4 * 4);
                float4 o;
                o.x = fmaxf(fmaf(t.x, s_red[fb + 0], s_red[D + fb + 0]), 0.f);
                o.y = fmaxf(fmaf(t.y, s_red[fb + 1], s_red[D + fb + 1]), 0.f);
                o.z = fmaxf(fmaf(t.z, s_red[fb + 2], s_red[D + fb + 2]), 0.f);
                o.w = fmaxf(fmaf(t.w, s_red[fb + 3], s_red[D + fb + 3]), 0.f);
                *(float4*)(g_h + (size_t)i4 * 4) = o;
            }
        }
        gsync();
    }

    // ---------- final pool ----------
    if (bid < NG) pool_block(g_h, NL, bid, srow);
    gsync();

    // ---------- score ----------
    for (int idx = gtid; idx < NG * 16; idx += GSZ) {
        int g = idx >> 4, o = idx & 15;
        float s = 0.f;
        #pragma unroll
        for (int l = 0; l < NL + 1; l++) {
            s += predb[l * 16 + o];
            const float* P  = g_pool + ((size_t)l * NG + g) * D;
            const float* Wp = predW + (size_t)l * D * 16;
            #pragma unroll
            for (int d = 0; d < D; d++) s = fmaf(P[d], Wp[d * 16 + o], s);
        }
        out[idx] = s;
    }
}

// ---------------- launch ----------------
extern "C" void kernel_launch(void* const* d_in, const int* in_sizes, int n_in,
                              void* d_out, int out_size)
{
    const float* x    = (const float*)d_in[0];
    const float* w    = (const float*)d_in[1];
    const int*   src  = (const int*)d_in[2];
    const int*   dst  = (const int*)d_in[3];
    const int*   gids = (const int*)d_in[4];
    const float* eps  = (const float*)d_in[5];
    const float* W1   = (const float*)d_in[6];
    const float* b1   = (const float*)d_in[7];
    const float* mbng = (const float*)d_in[8];
    const float* mbnb = (const float*)d_in[9];
    const float* W2   = (const float*)d_in[10];
    const float* b2   = (const float*)d_in[11];
    const float* bng  = (const float*)d_in[12];
    const float* bnb  = (const float*)d_in[13];
    const float* predW = (const float*)d_in[14];
    const float* predb = (const float*)d_in[15];
    float* out = (float*)d_out;

    k_gin<<<NBLK, TPB>>>(x, w, src, dst, gids, eps, W1, b1, mbng, mbnb,
                         W2, b2, bng, bnb, predW, predb, out);
}

// round 16
// speedup vs baseline: 1.1023x; 1.1023x over previous
#include <cuda_runtime.h>

#define NN 50000
#define NE 800000
#define NG 128
#define D  64
#define NL 4
#define BN_EPS 1e-5f

#define NBLK 296
#define TPB  512
#define NWARP (TPB / 32)          // 16
#define GSZ  (NBLK * TPB)         // 151552
#define NPW  4
#define NGRP (NN / NPW)           // 12500 exact
#define CHK  170                  // ceil(NN / NBLK)

typedef unsigned long long ull;

// ---------------- device scratch ----------------
__device__ int   g_deg[NN];
__device__ int   g_off[NN + 1];
__device__ int   g_cur[NN];
__device__ __align__(8) int2 g_edge[NE];      // {src, float_bits(w)}
__device__ __align__(16) float g_h[NN * D];
__device__ __align__(16) float g_t[NN * D];
__device__ float g_stats[NL * 4 * D];
__device__ float g_pool[(NL + 1) * NG * D];
__device__ int   g_gstart[NG + 1];
__device__ int   g_bsum[NBLK];
__device__ unsigned g_tick[8];
__device__ unsigned g_barcnt;
__device__ unsigned g_bargen;

// ---------------- f32x2 helpers ----------------
__device__ __forceinline__ ull ffma2(ull a, ull b, ull c) {
    ull d; asm("fma.rn.f32x2 %0, %1, %2, %3;" : "=l"(d) : "l"(a), "l"(b), "l"(c)); return d;
}
__device__ __forceinline__ ull fpack2(float lo, float hi) {
    ull d; asm("mov.b64 %0, {%1, %2};" : "=l"(d) : "f"(lo), "f"(hi)); return d;
}
__device__ __forceinline__ ull wdup(int bits) {
    float f = __int_as_float(bits);
    return fpack2(f, f);
}
__device__ __forceinline__ float2 funpack2(ull a) {
    float lo, hi; asm("mov.b64 {%0, %1}, %2;" : "=f"(lo), "=f"(hi) : "l"(a));
    return make_float2(lo, hi);
}

// ---------------- software grid barrier (all 296 CTAs resident) ----------------
__device__ __forceinline__ void gsync() {
    __syncthreads();
    if (threadIdx.x == 0) {
        unsigned gen = *(volatile unsigned*)&g_bargen;
        __threadfence();
        unsigned t = atomicAdd(&g_barcnt, 1u);
        if (t == NBLK - 1) {
            g_barcnt = 0;
            __threadfence();
            atomicAdd(&g_bargen, 1u);
        } else {
            while (*(volatile unsigned*)&g_bargen == gen) __nanosleep(64);
        }
        __threadfence();
    }
    __syncthreads();
}

// ---------------- graph pooling (block-wide, blocks < NG only) ----------------
__device__ __forceinline__ void pool_block(const float* __restrict__ h, int pidx, int g,
                                           float* scr) {
    const int tid = threadIdx.x, warp = tid >> 5, lane = tid & 31, f0 = lane * 2;
    const int n0 = g_gstart[g], n1 = g_gstart[g + 1];
    float2 acc = make_float2(0.f, 0.f);
    for (int n = n0 + warp; n < n1; n += NWARP) {
        float2 v = *(const float2*)(h + (size_t)n * D + f0);
        acc.x += v.x; acc.y += v.y;
    }
    scr[warp * D + f0] = acc.x;
    scr[warp * D + f0 + 1] = acc.y;
    __syncthreads();
    if (tid < D) {
        float s = 0.f;
        #pragma unroll
        for (int w2 = 0; w2 < NWARP; w2++) s += scr[w2 * D + tid];
        g_pool[((size_t)pidx * NG + g) * D + tid] = s;
    }
    __syncthreads();
}

__global__ __launch_bounds__(TPB, 2) void k_gin(
    const float* __restrict__ x, const float* __restrict__ w,
    const int* __restrict__ src, const int* __restrict__ dst,
    const int* __restrict__ gids, const float* __restrict__ epsv,
    const float* __restrict__ W1, const float* __restrict__ b1,
    const float* __restrict__ mbng, const float* __restrict__ mbnb,
    const float* __restrict__ W2, const float* __restrict__ b2,
    const float* __restrict__ bng, const float* __restrict__ bnb,
    const float* __restrict__ predW, const float* __restrict__ predb,
    float* __restrict__ out)
{
    __shared__ __align__(16) ull   sWp[2048];              // 16 KB (scan overlay)
    __shared__ __align__(16) float srow[NWARP * NPW * D];  // 16 KB (pool overlay)
    __shared__ float s_red[2 * D];

    const int tid = threadIdx.x, bid = blockIdx.x;
    const int gtid = bid * TPB + tid;
    const int warp = tid >> 5, lane = tid & 31;
    const int f0 = lane * 2;
    float* myrow = srow + warp * (NPW * D);

    // ---------- phase 0 ----------
    if (gtid < NN) g_deg[gtid] = 0;
    if (gtid < NL * 4 * D) g_stats[gtid] = 0.f;
    if (gtid < 8) g_tick[gtid] = 0u;
    if (bid == 0 && tid <= NG) {
        if (tid == NG) g_gstart[NG] = NN;
        else {
            int lo = 0, hi = NN;
            while (lo < hi) {
                int m = (lo + hi) >> 1;
                if (gids[m] < tid) lo = m + 1; else hi = m;
            }
            g_gstart[tid] = lo;
        }
    }
    gsync();

    // ---------- phase 1: degree histogram ----------
    for (int e = gtid; e < NE; e += GSZ) atomicAdd(&g_deg[dst[e]], 1);
    gsync();

    // ---------- phase 2a: block-local scan (CHK=170 <= 256) ----------
    int* s_scan = (int*)sWp;
    {
        int node = bid * CHK + tid;
        int dv = 0;
        if (tid < CHK && node < NN) dv = g_deg[node];
        if (tid < 256) s_scan[tid] = (tid < CHK) ? dv : 0;
        __syncthreads();
        for (int off = 1; off < 256; off <<= 1) {
            int v = 0;
            if (tid < 256 && tid >= off) v = s_scan[tid - off];
            __syncthreads();
            if (tid < 256) s_scan[tid] += v;
            __syncthreads();
        }
        if (tid < CHK && node < NN) g_off[node] = s_scan[tid] - dv;
        if (tid == 0) g_bsum[bid] = s_scan[255];
    }
    gsync();

    // ---------- phase 2b: scan 296 block totals ----------
    {
        int v = 0;
        if (tid < 512) { v = (tid < NBLK) ? g_bsum[tid] : 0; s_scan[tid] = v; }
        __syncthreads();
        for (int off = 1; off < 512; off <<= 1) {
            int u = 0;
            if (tid < 512 && tid >= off) u = s_scan[tid - off];
            __syncthreads();
            if (tid < 512) s_scan[tid] += u;
            __syncthreads();
        }
        if (tid < 512) s_scan[512 + tid] = s_scan[tid] - v;
        __syncthreads();
        int prefix = s_scan[512 + bid];
        int node = bid * CHK + tid;
        if (tid < CHK && node < NN) {
            int o = g_off[node] + prefix;
            g_off[node] = o; g_cur[node] = o;
        }
        if (bid == 0 && tid == 0) g_off[NN] = s_scan[NBLK - 1];
    }
    gsync();

    // ---------- phase 3: scatter edges + pool0 ----------
    for (int e = gtid; e < NE; e += GSZ) {
        int dn = dst[e];
        int p = atomicAdd(&g_cur[dn], 1);
        g_edge[p] = make_int2(src[e], __float_as_int(w[e]));
    }
    if (bid < NG) pool_block(x, 0, bid, srow);
    gsync();

    // ---------- layers ----------
    for (int l = 0; l < NL; l++) {
        // ===== phase A: aggregate (8-wide pipelined, ILP tail) + GEMM1 + stats1 =====
        {
            const float* W1l = W1 + (size_t)l * D * D;
            for (int i = tid; i < 2048; i += TPB) {
                int k2 = i >> 6, f = i & 63;
                sWp[i] = fpack2(W1l[(2 * k2) * D + f], W1l[(2 * k2 + 1) * D + f]);
            }
            if (tid < 2 * D) s_red[tid] = 0.f;
            __syncthreads();
            if (l > 0 && bid < NG) pool_block(g_h, l, bid, srow);
            __syncthreads();

            const float* hin = (l == 0) ? x : g_h;
            const float ep1 = 1.0f + epsv[l];
            const ull ep2 = fpack2(ep1, ep1);
            float2 bb = *(const float2*)(b1 + (size_t)l * D + f0);
            float2 psum = make_float2(0.f, 0.f), psq = make_float2(0.f, 0.f);

            for (;;) {
                unsigned g = 0;
                if (lane == 0) g = atomicAdd(&g_tick[l], 1u);
                g = __shfl_sync(0xffffffffu, g, 0);
                if (g >= NGRP) break;
                const int base = (int)g * NPW;

                // lane-owns-features gather: 8-wide pipeline + warp-uniform ILP tail
                #pragma unroll 1
                for (int j = 0; j < NPW; j++) {
                    const int n = base + j;
                    const int e0 = g_off[n], e1 = g_off[n + 1];
                    // self row loads early (independent of edge chain)
                    ull hn = *(const ull*)(hin + (size_t)n * D + f0);
                    ull acc = 0;
                    int e = e0;
                    if (e + 8 <= e1) {
                        int2 d0 = g_edge[e],     d1 = g_edge[e + 1];
                        int2 d2 = g_edge[e + 2], d3 = g_edge[e + 3];
                        int2 d4 = g_edge[e + 4], d5 = g_edge[e + 5];
                        int2 d6 = g_edge[e + 6], d7 = g_edge[e + 7];
                        #pragma unroll 1
                        for (; e + 16 <= e1; e += 8) {
                            int2 p0 = g_edge[e + 8],  p1 = g_edge[e + 9];
                            int2 p2 = g_edge[e + 10], p3 = g_edge[e + 11];
                            int2 p4 = g_edge[e + 12], p5 = g_edge[e + 13];
                            int2 p6 = g_edge[e + 14], p7 = g_edge[e + 15];
                            ull h0 = *(const ull*)(hin + (size_t)d0.x * D + f0);
                            ull h1 = *(const ull*)(hin + (size_t)d1.x * D + f0);
                            ull h2 = *(const ull*)(hin + (size_t)d2.x * D + f0);
                            ull h3 = *(const ull*)(hin + (size_t)d3.x * D + f0);
                            ull h4 = *(const ull*)(hin + (size_t)d4.x * D + f0);
                            ull h5 = *(const ull*)(hin + (size_t)d5.x * D + f0);
                            ull h6 = *(const ull*)(hin + (size_t)d6.x * D + f0);
                            ull h7 = *(const ull*)(hin + (size_t)d7.x * D + f0);
                            acc = ffma2(h0, wdup(d0.y), acc);
                            acc = ffma2(h1, wdup(d1.y), acc);
                            acc = ffma2(h2, wdup(d2.y), acc);
                            acc = ffma2(h3, wdup(d3.y), acc);
                            acc = ffma2(h4, wdup(d4.y), acc);
                            acc = ffma2(h5, wdup(d5.y), acc);
                            acc = ffma2(h6, wdup(d6.y), acc);
                            acc = ffma2(h7, wdup(d7.y), acc);
                            d0 = p0; d1 = p1; d2 = p2; d3 = p3;
                            d4 = p4; d5 = p5; d6 = p6; d7 = p7;
                        }
                        {
                            ull h0 = *(const ull*)(hin + (size_t)d0.x * D + f0);
                            ull h1 = *(const ull*)(hin + (size_t)d1.x * D + f0);
                            ull h2 = *(const ull*)(hin + (size_t)d2.x * D + f0);
                            ull h3 = *(const ull*)(hin + (size_t)d3.x * D + f0);
                            ull h4 = *(const ull*)(hin + (size_t)d4.x * D + f0);
                            ull h5 = *(const ull*)(hin + (size_t)d5.x * D + f0);
                            ull h6 = *(const ull*)(hin + (size_t)d6.x * D + f0);
                            ull h7 = *(const ull*)(hin + (size_t)d7.x * D + f0);
                            acc = ffma2(h0, wdup(d0.y), acc);
                            acc = ffma2(h1, wdup(d1.y), acc);
                            acc = ffma2(h2, wdup(d2.y), acc);
                            acc = ffma2(h3, wdup(d3.y), acc);
                            acc = ffma2(h4, wdup(d4.y), acc);
                            acc = ffma2(h5, wdup(d5.y), acc);
                            acc = ffma2(h6, wdup(d6.y), acc);
                            acc = ffma2(h7, wdup(d7.y), acc);
                            e += 8;
                        }
                    }
                    if (e + 4 <= e1) {
                        int2 d0 = g_edge[e],     d1 = g_edge[e + 1];
                        int2 d2 = g_edge[e + 2], d3 = g_edge[e + 3];
                        ull h0 = *(const ull*)(hin + (size_t)d0.x * D + f0);
                        ull h1 = *(const ull*)(hin + (size_t)d1.x * D + f0);
                        ull h2 = *(const ull*)(hin + (size_t)d2.x * D + f0);
                        ull h3 = *(const ull*)(hin + (size_t)d3.x * D + f0);
                        acc = ffma2(h0, wdup(d0.y), acc);
                        acc = ffma2(h1, wdup(d1.y), acc);
                        acc = ffma2(h2, wdup(d2.y), acc);
                        acc = ffma2(h3, wdup(d3.y), acc);
                        e += 4;
                    }
                    // warp-uniform ILP tail: rem in {0,1,2,3}
                    {
                        const int rem = e1 - e;
                        if (rem == 3) {
                            int2 d0 = g_edge[e], d1 = g_edge[e + 1], d2 = g_edge[e + 2];
                            ull h0 = *(const ull*)(hin + (size_t)d0.x * D + f0);
                            ull h1 = *(const ull*)(hin + (size_t)d1.x * D + f0);
                            ull h2 = *(const ull*)(hin + (size_t)d2.x * D + f0);
                            acc = ffma2(h0, wdup(d0.y), acc);
                            acc = ffma2(h1, wdup(d1.y), acc);
                            acc = ffma2(h2, wdup(d2.y), acc);
                        } else if (rem == 2) {
                            int2 d0 = g_edge[e], d1 = g_edge[e + 1];
                            ull h0 = *(const ull*)(hin + (size_t)d0.x * D + f0);
                            ull h1 = *(const ull*)(hin + (size_t)d1.x * D + f0);
                            acc = ffma2(h0, wdup(d0.y), acc);
                            acc = ffma2(h1, wdup(d1.y), acc);
                        } else if (rem == 1) {
                            int2 d0 = g_edge[e];
                            ull h0 = *(const ull*)(hin + (size_t)d0.x * D + f0);
                            acc = ffma2(h0, wdup(d0.y), acc);
                        }
                    }
                    *(ull*)(myrow + j * D + f0) = ffma2(hn, ep2, acc);
                }
                __syncwarp();

                // GEMM1: NPW-node blocking, 16B weight loads + 16B h broadcasts
                ull acc0[NPW], acc1[NPW];
                #pragma unroll
                for (int j = 0; j < NPW; j++) { acc0[j] = 0; acc1[j] = 0; }
                #pragma unroll
                for (int k2 = 0; k2 < 32; k2 += 2) {
                    ulonglong2 w0 = *(const ulonglong2*)(sWp + k2 * D + f0);
                    ulonglong2 w1 = *(const ulonglong2*)(sWp + (k2 + 1) * D + f0);
                    #pragma unroll
                    for (int j = 0; j < NPW; j++) {
                        ulonglong2 h2 = *(const ulonglong2*)(myrow + j * D + 2 * k2);
                        acc0[j] = ffma2(h2.x, w0.x, acc0[j]);
                        acc1[j] = ffma2(h2.x, w0.y, acc1[j]);
                        acc0[j] = ffma2(h2.y, w1.x, acc0[j]);
                        acc1[j] = ffma2(h2.y, w1.y, acc1[j]);
                    }
                }
                #pragma unroll
                for (int j = 0; j < NPW; j++) {
                    float2 u0 = funpack2(acc0[j]), u1 = funpack2(acc1[j]);
                    float ax = u0.x + u0.y + bb.x;
                    float ay = u1.x + u1.y + bb.y;
                    *(float2*)(g_t + (size_t)(base + j) * D + f0) = make_float2(ax, ay);
                    psum.x += ax; psum.y += ay;
                    psq.x = fmaf(ax, ax, psq.x);
                    psq.y = fmaf(ay, ay, psq.y);
                }
                __syncwarp();
            }
            atomicAdd(&s_red[f0], psum.x);
            atomicAdd(&s_red[f0 + 1], psum.y);
            atomicAdd(&s_red[D + f0], psq.x);
            atomicAdd(&s_red[D + f0 + 1], psq.y);
            __syncthreads();
            if (tid < D) {
                atomicAdd(&g_stats[(l * 4 + 0) * D + tid], s_red[tid]);
                atomicAdd(&g_stats[(l * 4 + 1) * D + tid], s_red[D + tid]);
            }
        }
        gsync();

        // ===== phase B: BN1 + ReLU + GEMM2 + stats2 =====
        {
            const float* W2l = W2 + (size_t)l * D * D;
            for (int i = tid; i < 2048; i += TPB) {
                int k2 = i >> 6, f = i & 63;
                sWp[i] = fpack2(W2l[(2 * k2) * D + f], W2l[(2 * k2 + 1) * D + f]);
            }
            if (tid < 2 * D) s_red[tid] = 0.f;
            __syncthreads();

            const float invN = 1.0f / NN;
            const float* sum1 = g_stats + (l * 4 + 0) * D;
            const float* sq1  = g_stats + (l * 4 + 1) * D;
            float mu0 = sum1[f0] * invN, mu1 = sum1[f0 + 1] * invN;
            float v0 = sq1[f0] * invN - mu0 * mu0;
            float v1 = sq1[f0 + 1] * invN - mu1 * mu1;
            float sc0 = mbng[l * D + f0] * rsqrtf(v0 + BN_EPS);
            float sc1 = mbng[l * D + f0 + 1] * rsqrtf(v1 + BN_EPS);
            float sh0 = mbnb[l * D + f0] - mu0 * sc0;
            float sh1 = mbnb[l * D + f0 + 1] - mu1 * sc1;
            float2 bb = *(const float2*)(b2 + (size_t)l * D + f0);
            float2 psum = make_float2(0.f, 0.f), psq = make_float2(0.f, 0.f);

            for (;;) {
                unsigned g = 0;
                if (lane == 0) g = atomicAdd(&g_tick[4 + l], 1u);
                g = __shfl_sync(0xffffffffu, g, 0);
                if (g >= NGRP) break;
                const int base = (int)g * NPW;

                #pragma unroll
                for (int j = 0; j < NPW; j++) {
                    float2 t2 = *(const float2*)(g_t + (size_t)(base + j) * D + f0);
                    float u0 = fmaxf(fmaf(t2.x, sc0, sh0), 0.f);
                    float u1 = fmaxf(fmaf(t2.y, sc1, sh1), 0.f);
                    *(float2*)(myrow + j * D + f0) = make_float2(u0, u1);
                }
                __syncwarp();

                ull acc0[NPW], acc1[NPW];
                #pragma unroll
                for (int j = 0; j < NPW; j++) { acc0[j] = 0; acc1[j] = 0; }
                #pragma unroll
                for (int k2 = 0; k2 < 32; k2 += 2) {
                    ulonglong2 w0 = *(const ulonglong2*)(sWp + k2 * D + f0);
                    ulonglong2 w1 = *(const ulonglong2*)(sWp + (k2 + 1) * D + f0);
                    #pragma unroll
                    for (int j = 0; j < NPW; j++) {
                        ulonglong2 h2 = *(const ulonglong2*)(myrow + j * D + 2 * k2);
                        acc0[j] = ffma2(h2.x, w0.x, acc0[j]);
                        acc1[j] = ffma2(h2.x, w0.y, acc1[j]);
                        acc0[j] = ffma2(h2.y, w1.x, acc0[j]);
                        acc1[j] = ffma2(h2.y, w1.y, acc1[j]);
                    }
                }
                #pragma unroll
                for (int j = 0; j < NPW; j++) {
                    float2 u0 = funpack2(acc0[j]), u1 = funpack2(acc1[j]);
                    float ax = u0.x + u0.y + bb.x;
                    float ay = u1.x + u1.y + bb.y;
                    *(float2*)(g_t + (size_t)(base + j) * D + f0) = make_float2(ax, ay);
                    psum.x += ax; psum.y += ay;
                    psq.x = fmaf(ax, ax, psq.x);
                    psq.y = fmaf(ay, ay, psq.y);
                }
                __syncwarp();
            }
            atomicAdd(&s_red[f0], psum.x);
            atomicAdd(&s_red[f0 + 1], psum.y);
            atomicAdd(&s_red[D + f0], psq.x);
            atomicAdd(&s_red[D + f0 + 1], psq.y);
            __syncthreads();
            if (tid < D) {
                atomicAdd(&g_stats[(l * 4 + 2) * D + tid], s_red[tid]);
                atomicAdd(&g_stats[(l * 4 + 3) * D + tid], s_red[D + tid]);
            }
        }
        gsync();

        // ===== phase C: outer BN + ReLU -> g_h =====
        {
            if (tid < D) {
                const float invN = 1.0f / NN;
                float mu = g_stats[(l * 4 + 2) * D + tid] * invN;
                float var = g_stats[(l * 4 + 3) * D + tid] * invN - mu * mu;
                float sc = bng[l * D + tid] * rsqrtf(var + BN_EPS);
                s_red[tid] = sc;
                s_red[D + tid] = bnb[l * D + tid] - mu * sc;
            }
            __syncthreads();
            for (int i4 = gtid; i4 < NN * (D / 4); i4 += GSZ) {
                int fb = (i4 & 15) * 4;
                float4 t = *(const float4*)(g_t + (size_t)i4 * 4);
                float4 o;
                o.x = fmaxf(fmaf(t.x, s_red[fb + 0], s_red[D + fb + 0]), 0.f);
                o.y = fmaxf(fmaf(t.y, s_red[fb + 1], s_red[D + fb + 1]), 0.f);
                o.z = fmaxf(fmaf(t.z, s_red[fb + 2], s_red[D + fb + 2]), 0.f);
                o.w = fmaxf(fmaf(t.w, s_red[fb + 3], s_red[D + fb + 3]), 0.f);
                *(float4*)(g_h + (size_t)i4 * 4) = o;
            }
        }
        gsync();
    }

    // ---------- final pool ----------
    if (bid < NG) pool_block(g_h, NL, bid, srow);
    gsync();

    // ---------- score ----------
    for (int idx = gtid; idx < NG * 16; idx += GSZ) {
        int g = idx >> 4, o = idx & 15;
        float s = 0.f;
        #pragma unroll
        for (int l = 0; l < NL + 1; l++) {
            s += predb[l * 16 + o];
            const float* P  = g_pool + ((size_t)l * NG + g) * D;
            const float* Wp = predW + (size_t)l * D * 16;
            #pragma unroll
            for (int d = 0; d < D; d++) s = fmaf(P[d], Wp[d * 16 + o], s);
        }
        out[idx] = s;
    }
}

// ---------------- launch ----------------
extern "C" void kernel_launch(void* const* d_in, const int* in_sizes, int n_in,
                              void* d_out, int out_size)
{
    const float* x    = (const float*)d_in[0];
    const float* w    = (const float*)d_in[1];
    const int*   src  = (const int*)d_in[2];
    const int*   dst  = (const int*)d_in[3];
    const int*   gids = (const int*)d_in[4];
    const float* eps  = (const float*)d_in[5];
    const float* W1   = (const float*)d_in[6];
    const float* b1   = (const float*)d_in[7];
    const float* mbng = (const float*)d_in[8];
    const float* mbnb = (const float*)d_in[9];
    const float* W2   = (const float*)d_in[10];
    const float* b2   = (const float*)d_in[11];
    const float* bng  = (const float*)d_in[12];
    const float* bnb  = (const float*)d_in[13];
    const float* predW = (const float*)d_in[14];
    const float* predb = (const float*)d_in[15];
    float* out = (float*)d_out;

    k_gin<<<NBLK, TPB>>>(x, w, src, dst, gids, eps, W1, b1, mbng, mbnb,
                         W2, b2, bng, bnb, predW, predb, out);
}